// round 5
// baseline (speedup 1.0000x reference)
#include <cuda_runtime.h>
#include <cuda_fp16.h>
#include <math.h>

#define NMAX 100000
#define EMAX 1600000
#define EPS 1e-5f
#define SCAN_BLK 1024
#define MAX_BLKS 128   // ceil(100000/1024)=98 <= 128

// ---- device scratch (no allocations allowed) ----
__device__ int      g_deg [NMAX];
__device__ int      g_off [NMAX + 1];
__device__ int      g_cur [NMAX];
__device__ unsigned g_state[MAX_BLKS];             // lookback: (flag<<28)|sum
__device__ float    g_dinv[NMAX];
__device__ int      g_csr [EMAX];                  // col index only
__device__ __half   g_h   [(size_t)NMAX * 64];     // dinv-prescaled GEMM output (fp16)
__device__ float    g_agg [(size_t)NMAX * 64];

// ------------------- build step 1: zero -------------------
__global__ void k_zero(int N) {
    int i = blockIdx.x * blockDim.x + threadIdx.x;
    if (i < N) g_deg[i] = 0;
    if (i < MAX_BLKS) g_state[i] = 0;              // reset lookback state每launch
}

__global__ void k_count(const int* __restrict__ row, int E) {
    int e = blockIdx.x * blockDim.x + threadIdx.x;
    if (e < E) atomicAdd(&g_deg[row[e]], 1);
}

// ------------- single-kernel decoupled-lookback scan + dinv -------------
__global__ __launch_bounds__(SCAN_BLK)
void k_scan_lb(int N, int E) {
    __shared__ int warp_sums[32];
    __shared__ int s_prefix;

    int bid  = blockIdx.x;
    int tid  = threadIdx.x;
    int lane = tid & 31;
    int wid  = tid >> 5;
    int i    = bid * SCAN_BLK + tid;

    int v = (i < N) ? g_deg[i] : 0;
    if (i < N) g_dinv[i] = rsqrtf((float)v + 1.0f);   // +1 = self loop

    // warp inclusive scan
    int x = v;
    #pragma unroll
    for (int d = 1; d < 32; d <<= 1) {
        int t = __shfl_up_sync(0xFFFFFFFFu, x, d);
        if (lane >= d) x += t;
    }
    if (lane == 31) warp_sums[wid] = x;
    __syncthreads();
    if (wid == 0) {
        int y = warp_sums[lane];
        #pragma unroll
        for (int d = 1; d < 32; d <<= 1) {
            int t = __shfl_up_sync(0xFFFFFFFFu, y, d);
            if (lane >= d) y += t;
        }
        warp_sums[lane] = y;                       // inclusive warp prefix
    }
    __syncthreads();

    int block_incl  = x + (wid > 0 ? warp_sums[wid - 1] : 0);
    int block_total = warp_sums[31];

    if (tid == 0) {
        if (bid == 0) {
            s_prefix = 0;
            atomicExch(&g_state[0], (2u << 28) | (unsigned)block_total);
        } else {
            atomicExch(&g_state[bid], (1u << 28) | (unsigned)block_total);
            int run = 0;
            int j = bid - 1;
            while (true) {
                unsigned st = atomicAdd(&g_state[j], 0u);
                unsigned f = st >> 28;
                if (f == 0) { __nanosleep(40); continue; }
                run += (int)(st & 0x0FFFFFFFu);
                if (f == 2u) break;
                j--;
            }
            s_prefix = run;
            atomicExch(&g_state[bid], (2u << 28) | (unsigned)(run + block_total));
        }
        if (bid == 0) g_off[N] = E;
    }
    __syncthreads();

    int ex = s_prefix + block_incl - v;            // exclusive prefix
    if (i < N) { g_off[i] = ex; g_cur[i] = ex; }
}

__global__ void k_build(const int* __restrict__ row, const int* __restrict__ col, int E) {
    int e = blockIdx.x * blockDim.x + threadIdx.x;
    if (e >= E) return;
    int pos = atomicAdd(&g_cur[row[e]], 1);
    g_csr[pos] = col[e];
}

// ------------------- GEMM: hs = (in @ W) * dinv[row], fp16 out -------------------
// 256 threads, 64 rows/block. K-paired accumulation via fma.rn.f32x2:
// acc pair = {sum over even k, sum over odd k}; both operands are contiguous
// 8B smem pairs (X row-major, W transposed to [c][k] pad-66), zero pack MOVs.
#define GEMM_ROWS 64

__global__ __launch_bounds__(256)
void k_gemm(const float* __restrict__ in, const float* __restrict__ W,
            __half* __restrict__ out, int N)
{
    __shared__ float Wt[64][66];     // [c][k], padded: 8B aligned rows, conflict-free
    __shared__ float Xs[GEMM_ROWS][64];

    int tid = threadIdx.x;
    int row0 = blockIdx.x * GEMM_ROWS;

    #pragma unroll
    for (int i = tid; i < 64 * 64; i += 256) {
        int k = i >> 6, c = i & 63;
        Wt[c][k] = W[i];
    }

    #pragma unroll
    for (int i = tid; i < GEMM_ROWS * 16; i += 256) {
        int r = i >> 4, k4 = (i & 15);
        int gr = row0 + r;
        float4 v = (gr < N) ? reinterpret_cast<const float4*>(in)[(size_t)gr * 16 + k4]
                            : make_float4(0.f, 0.f, 0.f, 0.f);
        reinterpret_cast<float4*>(&Xs[r][0])[k4] = v;
    }
    __syncthreads();

    int cg = tid & 15;    // cols: cg, cg+16, cg+32, cg+48
    int rg = tid >> 4;    // rows: rg*4 .. +3
    int r0 = rg * 4;

    unsigned long long acc[4][4];
    #pragma unroll
    for (int a = 0; a < 4; a++)
        #pragma unroll
        for (int b = 0; b < 4; b++)
            acc[a][b] = 0ULL;      // packed (0.f, 0.f)

    #pragma unroll 8
    for (int kp = 0; kp < 32; kp++) {
        unsigned long long xv[4], wv[4];
        #pragma unroll
        for (int a = 0; a < 4; a++)
            xv[a] = *reinterpret_cast<const unsigned long long*>(&Xs[r0 + a][kp * 2]);
        #pragma unroll
        for (int b = 0; b < 4; b++)
            wv[b] = *reinterpret_cast<const unsigned long long*>(&Wt[cg + 16 * b][kp * 2]);
        #pragma unroll
        for (int a = 0; a < 4; a++)
            #pragma unroll
            for (int b = 0; b < 4; b++)
                asm("fma.rn.f32x2 %0, %1, %2, %0;"
                    : "+l"(acc[a][b]) : "l"(xv[a]), "l"(wv[b]));
    }

    #pragma unroll
    for (int a = 0; a < 4; a++) {
        int gr = row0 + r0 + a;
        if (gr < N) {
            float di = g_dinv[gr];
            #pragma unroll
            for (int b = 0; b < 4; b++) {
                float lo, hi;
                asm("mov.b64 {%0,%1}, %2;" : "=f"(lo), "=f"(hi) : "l"(acc[a][b]));
                out[(size_t)gr * 64 + cg + 16 * b] = __float2half_rn((lo + hi) * di);
            }
        }
    }
}

// ------------------- pull aggregation (fp16 gathers, fp32 accumulate) ----------
// out[i,:] = act( bias + dinv_i * ( hs[i,:] + sum_p hs[csr[p],:] ) )
// 16 threads/node, 4 channels (8B) per lane. Full 16-edge chunks use a
// predicate-free path with pairwise HADD2 (2 edges summed in fp16 before
// promoting to fp32); tail handled per-edge in fp32.
__global__ __launch_bounds__(256)
void k_pull(const __half* __restrict__ h, const float* __restrict__ bias,
            float* __restrict__ out, int N,
            const float* __restrict__ gam, const float* __restrict__ bet,
            const float* __restrict__ mu,  const float* __restrict__ var,
            int use_bn)
{
    int idx = blockIdx.x * blockDim.x + threadIdx.x;
    if (idx >= N * 16) return;
    int i = idx >> 4, k = idx & 15;

    const uint2* h2 = reinterpret_cast<const uint2*>(h);   // 16 uint2 per row
    unsigned mask = 0xFFFFu << (threadIdx.x & 16);

    float4 acc;
    {   // self term
        uint2 sv = __ldg(&h2[(size_t)i * 16 + k]);
        float2 f0 = __half22float2(*reinterpret_cast<__half2*>(&sv.x));
        float2 f1 = __half22float2(*reinterpret_cast<__half2*>(&sv.y));
        acc.x = f0.x; acc.y = f0.y; acc.z = f1.x; acc.w = f1.y;
    }

    int p   = g_off[i];
    int end = g_off[i + 1];

    // full chunks: 16 edges, no predicates, pairwise fp16 pre-sum
    while (p + 16 <= end) {
        int cidx = g_csr[p + k];                 // coalesced 64B
        #pragma unroll
        for (int jp = 0; jp < 8; jp++) {
            int c0 = __shfl_sync(mask, cidx, 2 * jp,     16);
            int c1 = __shfl_sync(mask, cidx, 2 * jp + 1, 16);
            uint2 v0 = __ldg(&h2[(size_t)c0 * 16 + k]);
            uint2 v1 = __ldg(&h2[(size_t)c1 * 16 + k]);
            __half2 s0 = __hadd2(*reinterpret_cast<__half2*>(&v0.x),
                                 *reinterpret_cast<__half2*>(&v1.x));
            __half2 s1 = __hadd2(*reinterpret_cast<__half2*>(&v0.y),
                                 *reinterpret_cast<__half2*>(&v1.y));
            float2 f0 = __half22float2(s0);
            float2 f1 = __half22float2(s1);
            acc.x += f0.x; acc.y += f0.y; acc.z += f1.x; acc.w += f1.y;
        }
        p += 16;
    }

    // tail (< 16 edges), per-edge fp32
    if (p < end) {
        int m = end - p;
        int pk = p + k;
        int cidx = g_csr[(pk < end) ? pk : p];
        #pragma unroll
        for (int j = 0; j < 15; j++) {
            if (j < m) {                         // uniform within 16-lane group
                int c = __shfl_sync(mask, cidx, j, 16);
                uint2 v = __ldg(&h2[(size_t)c * 16 + k]);
                float2 f0 = __half22float2(*reinterpret_cast<__half2*>(&v.x));
                float2 f1 = __half22float2(*reinterpret_cast<__half2*>(&v.y));
                acc.x += f0.x; acc.y += f0.y; acc.z += f1.x; acc.w += f1.y;
            }
        }
    }

    float di = g_dinv[i];
    float4 bv = reinterpret_cast<const float4*>(bias)[k];
    acc.x = fmaf(acc.x, di, bv.x);
    acc.y = fmaf(acc.y, di, bv.y);
    acc.z = fmaf(acc.z, di, bv.z);
    acc.w = fmaf(acc.w, di, bv.w);

    if (use_bn) {
        int k4 = k << 2;
        #pragma unroll
        for (int j = 0; j < 4; j++) {
            float a = gam[k4 + j] * rsqrtf(var[k4 + j] + EPS);
            float c = bet[k4 + j] - mu[k4 + j] * a;
            float* f = (&acc.x) + j;
            *f = fmaxf(fmaf(*f, a, c), 0.0f);
        }
    }

    reinterpret_cast<float4*>(out)[(size_t)i * 16 + k] = acc;
}

// ------------------- launch -------------------
extern "C" void kernel_launch(void* const* d_in, const int* in_sizes, int n_in,
                              void* d_out, int out_size)
{
    const float* x   = (const float*)d_in[0];
    const int*   ei  = (const int*)  d_in[1];
    const float* W1  = (const float*)d_in[2];
    const float* b1  = (const float*)d_in[3];
    const float* g1  = (const float*)d_in[4];
    const float* be1 = (const float*)d_in[5];
    const float* m1  = (const float*)d_in[6];
    const float* v1  = (const float*)d_in[7];
    const float* W2  = (const float*)d_in[8];
    const float* b2  = (const float*)d_in[9];
    const float* g2  = (const float*)d_in[10];
    const float* be2 = (const float*)d_in[11];
    const float* m2  = (const float*)d_in[12];
    const float* v2  = (const float*)d_in[13];
    const float* W3  = (const float*)d_in[14];
    const float* b3  = (const float*)d_in[15];

    int N = in_sizes[0] / 64;
    int E = in_sizes[1] / 2;

    const int* row = ei;
    const int* col = ei + E;

    float* out  = (float*)d_out;
    float* emb  = out;                      // global_embeddings [N,64]
    float* pred = out + (size_t)N * 64;     // hc_predictions    [N,64]

    __half* p_h = nullptr;
    float*  p_agg = nullptr;
    cudaGetSymbolAddress((void**)&p_h,   g_h);
    cudaGetSymbolAddress((void**)&p_agg, g_agg);

    const int T = 256;
    int gN   = (N + T - 1) / T;
    int gE   = (E + T - 1) / T;
    int gN16 = (N * 16 + T - 1) / T;
    int gG   = (N + GEMM_ROWS - 1) / GEMM_ROWS;
    int nb   = (N + SCAN_BLK - 1) / SCAN_BLK;

    // ---- CSR build (once per launch, reused by all 3 convs) ----
    k_zero   <<<gN, T>>>(N);
    k_count  <<<gE, T>>>(row, E);
    k_scan_lb<<<nb, SCAN_BLK>>>(N, E);      // scan + dinv + cursors, one kernel
    k_build  <<<gE, T>>>(row, col, E);

    // ---- layer 1: h = relu(bn1(conv(x, W1) + b1)) ----
    k_gemm<<<gG,   T>>>(x, W1, p_h, N);
    k_pull<<<gN16, T>>>(p_h, b1, p_agg, N, g1, be1, m1, v1, 1);

    // ---- layer 2: emb = relu(bn2(conv(h, W2) + b2)) -> d_out[0:N*64] ----
    k_gemm<<<gG,   T>>>(p_agg, W2, p_h, N);
    k_pull<<<gN16, T>>>(p_h, b2, emb, N, g2, be2, m2, v2, 1);

    // ---- layer 3: pred = conv(emb, W3) + b3 -> d_out[N*64:] ----
    k_gemm<<<gG,   T>>>(emb, W3, p_h, N);
    k_pull<<<gN16, T>>>(p_h, b3, pred, N, nullptr, nullptr, nullptr, nullptr, 0);
}

// round 6
// speedup vs baseline: 1.1365x; 1.1365x over previous
#include <cuda_runtime.h>
#include <cuda_fp16.h>
#include <math.h>

#define NMAX 100000
#define EMAX 1600000
#define CSRMAX (EMAX + 16 * NMAX)    // padded CSR capacity
#define EPS 1e-5f
#define SCAN_BLK 1024
#define MAX_BLKS 128                 // ceil(100000/1024)=98 <= 128

// ---- device scratch (no allocations allowed) ----
__device__ int      g_deg [NMAX];
__device__ int      g_off [NMAX + 1];
__device__ int      g_cur [NMAX];
__device__ unsigned g_state[MAX_BLKS];                  // lookback: (flag<<28)|sum
__device__ float    g_dinv[NMAX];
__device__ int      g_csr [CSRMAX];                     // col index, padded/16
__device__ __half   g_h   [(size_t)(NMAX + 1) * 64];    // +1: zero dummy row
__device__ float    g_agg [(size_t)NMAX * 64];

// ---------- zero/prefill: deg=0, state=0, csr=NMAX (dummy), dummy h row=0 ----------
__global__ void k_zero(int N) {
    int i = blockIdx.x * blockDim.x + threadIdx.x;
    if (i < CSRMAX) g_csr[i] = NMAX;
    if (i < N) g_deg[i] = 0;
    if (i < MAX_BLKS) g_state[i] = 0;
    if (i < 64) g_h[(size_t)NMAX * 64 + i] = __float2half(0.0f);
}

// ---------- degree count: 4 independent atomics per thread (MLP=4) ----------
__global__ void k_count(const int* __restrict__ row, int E) {
    int t = blockIdx.x * blockDim.x + threadIdx.x;
    int stride = gridDim.x * blockDim.x;
    #pragma unroll
    for (int j = 0; j < 4; j++) {
        int e = t + j * stride;
        if (e < E) atomicAdd(&g_deg[row[e]], 1);
    }
}

// ---------- decoupled-lookback scan over PADDED degrees + dinv ----------
__global__ __launch_bounds__(SCAN_BLK)
void k_scan_lb(int N) {
    __shared__ int warp_sums[32];
    __shared__ int s_prefix;

    int bid  = blockIdx.x;
    int tid  = threadIdx.x;
    int lane = tid & 31;
    int wid  = tid >> 5;
    int i    = bid * SCAN_BLK + tid;

    int v = (i < N) ? g_deg[i] : 0;
    if (i < N) g_dinv[i] = rsqrtf((float)v + 1.0f);   // +1 = self loop
    int vp = (v + 15) & ~15;                          // padded degree

    int x = vp;
    #pragma unroll
    for (int d = 1; d < 32; d <<= 1) {
        int t = __shfl_up_sync(0xFFFFFFFFu, x, d);
        if (lane >= d) x += t;
    }
    if (lane == 31) warp_sums[wid] = x;
    __syncthreads();
    if (wid == 0) {
        int y = warp_sums[lane];
        #pragma unroll
        for (int d = 1; d < 32; d <<= 1) {
            int t = __shfl_up_sync(0xFFFFFFFFu, y, d);
            if (lane >= d) y += t;
        }
        warp_sums[lane] = y;
    }
    __syncthreads();

    int block_incl  = x + (wid > 0 ? warp_sums[wid - 1] : 0);
    int block_total = warp_sums[31];

    if (tid == 0) {
        if (bid == 0) {
            s_prefix = 0;
            atomicExch(&g_state[0], (2u << 28) | (unsigned)block_total);
        } else {
            atomicExch(&g_state[bid], (1u << 28) | (unsigned)block_total);
            int run = 0;
            int j = bid - 1;
            while (true) {
                unsigned st = atomicAdd(&g_state[j], 0u);
                unsigned f = st >> 28;
                if (f == 0) { __nanosleep(40); continue; }
                run += (int)(st & 0x0FFFFFFFu);
                if (f == 2u) break;
                j--;
            }
            s_prefix = run;
            atomicExch(&g_state[bid], (2u << 28) | (unsigned)(run + block_total));
        }
        if (bid == (int)gridDim.x - 1)
            g_off[N] = s_prefix + block_total;        // total padded edges
    }
    __syncthreads();

    int ex = s_prefix + block_incl - vp;              // exclusive prefix (16-aligned)
    if (i < N) { g_off[i] = ex; g_cur[i] = ex; }
}

// ---------- scatter: 4 independent atomics per thread (MLP=4) ----------
__global__ void k_build(const int* __restrict__ row, const int* __restrict__ col, int E) {
    int t = blockIdx.x * blockDim.x + threadIdx.x;
    int stride = gridDim.x * blockDim.x;
    #pragma unroll
    for (int j = 0; j < 4; j++) {
        int e = t + j * stride;
        if (e < E) {
            int pos = atomicAdd(&g_cur[row[e]], 1);
            g_csr[pos] = col[e];
        }
    }
}

// ------------------- GEMM: hs = (in @ W) * dinv[row], fp16 out -------------------
#define GEMM_ROWS 64

__global__ __launch_bounds__(256)
void k_gemm(const float* __restrict__ in, const float* __restrict__ W,
            __half* __restrict__ out, int N)
{
    __shared__ float Wt[64][66];     // [c][k], padded: 8B aligned, conflict-free
    __shared__ float Xs[GEMM_ROWS][64];

    int tid = threadIdx.x;
    int row0 = blockIdx.x * GEMM_ROWS;

    #pragma unroll
    for (int i = tid; i < 64 * 64; i += 256) {
        int k = i >> 6, c = i & 63;
        Wt[c][k] = W[i];
    }

    #pragma unroll
    for (int i = tid; i < GEMM_ROWS * 16; i += 256) {
        int r = i >> 4, k4 = (i & 15);
        int gr = row0 + r;
        float4 v = (gr < N) ? reinterpret_cast<const float4*>(in)[(size_t)gr * 16 + k4]
                            : make_float4(0.f, 0.f, 0.f, 0.f);
        reinterpret_cast<float4*>(&Xs[r][0])[k4] = v;
    }
    __syncthreads();

    int cg = tid & 15;
    int rg = tid >> 4;
    int r0 = rg * 4;

    unsigned long long acc[4][4];
    #pragma unroll
    for (int a = 0; a < 4; a++)
        #pragma unroll
        for (int b = 0; b < 4; b++)
            acc[a][b] = 0ULL;

    #pragma unroll 8
    for (int kp = 0; kp < 32; kp++) {
        unsigned long long xv[4], wv[4];
        #pragma unroll
        for (int a = 0; a < 4; a++)
            xv[a] = *reinterpret_cast<const unsigned long long*>(&Xs[r0 + a][kp * 2]);
        #pragma unroll
        for (int b = 0; b < 4; b++)
            wv[b] = *reinterpret_cast<const unsigned long long*>(&Wt[cg + 16 * b][kp * 2]);
        #pragma unroll
        for (int a = 0; a < 4; a++)
            #pragma unroll
            for (int b = 0; b < 4; b++)
                asm("fma.rn.f32x2 %0, %1, %2, %0;"
                    : "+l"(acc[a][b]) : "l"(xv[a]), "l"(wv[b]));
    }

    #pragma unroll
    for (int a = 0; a < 4; a++) {
        int gr = row0 + r0 + a;
        if (gr < N) {
            float di = g_dinv[gr];
            #pragma unroll
            for (int b = 0; b < 4; b++) {
                float lo, hi;
                asm("mov.b64 {%0,%1}, %2;" : "=f"(lo), "=f"(hi) : "l"(acc[a][b]));
                out[(size_t)gr * 64 + cg + 16 * b] = __float2half_rn((lo + hi) * di);
            }
        }
    }
}

// ------------------- pull aggregation (fp16 gathers, fp32 accumulate) ----------
// Edge lists are padded to multiples of 16 with dummy index NMAX (zero row),
// 16-aligned offsets. Chunk = 4 aligned int4 broadcast loads + 16 unconditional
// gathers; no shuffles, no predicates, no tail.
__global__ __launch_bounds__(256)
void k_pull(const __half* __restrict__ h, const float* __restrict__ bias,
            float* __restrict__ out, int N,
            const float* __restrict__ gam, const float* __restrict__ bet,
            const float* __restrict__ mu,  const float* __restrict__ var,
            int use_bn)
{
    int idx = blockIdx.x * blockDim.x + threadIdx.x;
    if (idx >= N * 16) return;
    int i = idx >> 4, k = idx & 15;

    const uint2* h2 = reinterpret_cast<const uint2*>(h);   // 16 uint2 per row

    float4 acc;
    {   // self term
        uint2 sv = __ldg(&h2[(size_t)i * 16 + k]);
        float2 f0 = __half22float2(*reinterpret_cast<__half2*>(&sv.x));
        float2 f1 = __half22float2(*reinterpret_cast<__half2*>(&sv.y));
        acc.x = f0.x; acc.y = f0.y; acc.z = f1.x; acc.w = f1.y;
    }

    int p   = g_off[i];
    int end = g_off[i + 1];

    for (; p < end; p += 16) {
        const int4* c4 = reinterpret_cast<const int4*>(&g_csr[p]);   // 16B aligned
        int4 a0 = __ldg(c4 + 0);
        int4 a1 = __ldg(c4 + 1);
        int4 a2 = __ldg(c4 + 2);
        int4 a3 = __ldg(c4 + 3);
        int cj[16] = { a0.x, a0.y, a0.z, a0.w,
                       a1.x, a1.y, a1.z, a1.w,
                       a2.x, a2.y, a2.z, a2.w,
                       a3.x, a3.y, a3.z, a3.w };

        #pragma unroll
        for (int jp = 0; jp < 8; jp++) {
            uint2 v0 = __ldg(&h2[(size_t)cj[2 * jp]     * 16 + k]);
            uint2 v1 = __ldg(&h2[(size_t)cj[2 * jp + 1] * 16 + k]);
            __half2 s0 = __hadd2(*reinterpret_cast<__half2*>(&v0.x),
                                 *reinterpret_cast<__half2*>(&v1.x));
            __half2 s1 = __hadd2(*reinterpret_cast<__half2*>(&v0.y),
                                 *reinterpret_cast<__half2*>(&v1.y));
            float2 f0 = __half22float2(s0);
            float2 f1 = __half22float2(s1);
            acc.x += f0.x; acc.y += f0.y; acc.z += f1.x; acc.w += f1.y;
        }
    }

    float di = g_dinv[i];
    float4 bv = reinterpret_cast<const float4*>(bias)[k];
    acc.x = fmaf(acc.x, di, bv.x);
    acc.y = fmaf(acc.y, di, bv.y);
    acc.z = fmaf(acc.z, di, bv.z);
    acc.w = fmaf(acc.w, di, bv.w);

    if (use_bn) {
        int k4 = k << 2;
        #pragma unroll
        for (int j = 0; j < 4; j++) {
            float a = gam[k4 + j] * rsqrtf(var[k4 + j] + EPS);
            float c = bet[k4 + j] - mu[k4 + j] * a;
            float* f = (&acc.x) + j;
            *f = fmaxf(fmaf(*f, a, c), 0.0f);
        }
    }

    reinterpret_cast<float4*>(out)[(size_t)i * 16 + k] = acc;
}

// ------------------- launch -------------------
extern "C" void kernel_launch(void* const* d_in, const int* in_sizes, int n_in,
                              void* d_out, int out_size)
{
    const float* x   = (const float*)d_in[0];
    const int*   ei  = (const int*)  d_in[1];
    const float* W1  = (const float*)d_in[2];
    const float* b1  = (const float*)d_in[3];
    const float* g1  = (const float*)d_in[4];
    const float* be1 = (const float*)d_in[5];
    const float* m1  = (const float*)d_in[6];
    const float* v1  = (const float*)d_in[7];
    const float* W2  = (const float*)d_in[8];
    const float* b2  = (const float*)d_in[9];
    const float* g2  = (const float*)d_in[10];
    const float* be2 = (const float*)d_in[11];
    const float* m2  = (const float*)d_in[12];
    const float* v2  = (const float*)d_in[13];
    const float* W3  = (const float*)d_in[14];
    const float* b3  = (const float*)d_in[15];

    int N = in_sizes[0] / 64;
    int E = in_sizes[1] / 2;

    const int* row = ei;
    const int* col = ei + E;

    float* out  = (float*)d_out;
    float* emb  = out;                      // global_embeddings [N,64]
    float* pred = out + (size_t)N * 64;     // hc_predictions    [N,64]

    __half* p_h = nullptr;
    float*  p_agg = nullptr;
    cudaGetSymbolAddress((void**)&p_h,   g_h);
    cudaGetSymbolAddress((void**)&p_agg, g_agg);

    const int T = 256;
    int gZ   = (CSRMAX + T - 1) / T;
    int gE4  = (E + 4 * T - 1) / (4 * T);
    int gN16 = (N * 16 + T - 1) / T;
    int gG   = (N + GEMM_ROWS - 1) / GEMM_ROWS;
    int nb   = (N + SCAN_BLK - 1) / SCAN_BLK;

    // ---- CSR build (once per launch, reused by all 3 convs) ----
    k_zero   <<<gZ,  T>>>(N);
    k_count  <<<gE4, T>>>(row, E);
    k_scan_lb<<<nb, SCAN_BLK>>>(N);
    k_build  <<<gE4, T>>>(row, col, E);

    // ---- layer 1: h = relu(bn1(conv(x, W1) + b1)) ----
    k_gemm<<<gG,   T>>>(x, W1, p_h, N);
    k_pull<<<gN16, T>>>(p_h, b1, p_agg, N, g1, be1, m1, v1, 1);

    // ---- layer 2: emb = relu(bn2(conv(h, W2) + b2)) -> d_out[0:N*64] ----
    k_gemm<<<gG,   T>>>(p_agg, W2, p_h, N);
    k_pull<<<gN16, T>>>(p_h, b2, emb, N, g2, be2, m2, v2, 1);

    // ---- layer 3: pred = conv(emb, W3) + b3 -> d_out[N*64:] ----
    k_gemm<<<gG,   T>>>(emb, W3, p_h, N);
    k_pull<<<gN16, T>>>(p_h, b3, pred, N, nullptr, nullptr, nullptr, nullptr, 0);
}

// round 7
// speedup vs baseline: 1.1607x; 1.0213x over previous
#include <cuda_runtime.h>
#include <cuda_fp16.h>
#include <math.h>

#define NMAX 100000
#define EMAX 1600000
#define CSRMAX (EMAX + 16 * NMAX)    // padded CSR capacity (multiple of 4)
#define EPS 1e-5f
#define SCAN_BLK 1024
#define MAX_BLKS 128                 // ceil(100000/1024)=98 <= 128

// ---- device scratch (no allocations allowed) ----
__device__ int      g_deg [NMAX];
__device__ int      g_off [NMAX + 1];
__device__ int      g_cur [NMAX];
__device__ unsigned g_state[MAX_BLKS];                  // lookback: (flag<<28)|sum
__device__ float    g_dinv[NMAX];
__device__ int      g_csr [CSRMAX];                     // col index, padded/16
__device__ __half   g_h   [(size_t)(NMAX + 1) * 64];    // +1: zero dummy row
__device__ float    g_agg [(size_t)NMAX * 64];

// ---------- zeroA: deg=0, lookback state=0, dummy h row=0 ----------
__global__ void k_zeroA(int N) {
    int i = blockIdx.x * blockDim.x + threadIdx.x;
    if (i < N) g_deg[i] = 0;
    if (i < MAX_BLKS) g_state[i] = 0;
    if (i < 16) reinterpret_cast<uint2*>(&g_h[(size_t)NMAX * 64])[i] = make_uint2(0u, 0u);
}

// ---------- zeroCSR: fill padded CSR with dummy index (int4 stores) ----------
__global__ void k_zeroCSR() {
    int i = blockIdx.x * blockDim.x + threadIdx.x;
    if (i < CSRMAX / 4)
        reinterpret_cast<int4*>(g_csr)[i] = make_int4(NMAX, NMAX, NMAX, NMAX);
}

// ---------- degree count: 4 independent atomics per thread ----------
__global__ void k_count(const int* __restrict__ row, int E) {
    int t = blockIdx.x * blockDim.x + threadIdx.x;
    int stride = gridDim.x * blockDim.x;
    #pragma unroll
    for (int j = 0; j < 4; j++) {
        int e = t + j * stride;
        if (e < E) atomicAdd(&g_deg[row[e]], 1);
    }
}

// ---------- decoupled-lookback scan over PADDED degrees + dinv ----------
__global__ __launch_bounds__(SCAN_BLK)
void k_scan_lb(int N) {
    __shared__ int warp_sums[32];
    __shared__ int s_prefix;

    int bid  = blockIdx.x;
    int tid  = threadIdx.x;
    int lane = tid & 31;
    int wid  = tid >> 5;
    int i    = bid * SCAN_BLK + tid;

    int v = (i < N) ? g_deg[i] : 0;
    if (i < N) g_dinv[i] = rsqrtf((float)v + 1.0f);   // +1 = self loop
    int vp = (v + 15) & ~15;                          // padded degree

    int x = vp;
    #pragma unroll
    for (int d = 1; d < 32; d <<= 1) {
        int t = __shfl_up_sync(0xFFFFFFFFu, x, d);
        if (lane >= d) x += t;
    }
    if (lane == 31) warp_sums[wid] = x;
    __syncthreads();
    if (wid == 0) {
        int y = warp_sums[lane];
        #pragma unroll
        for (int d = 1; d < 32; d <<= 1) {
            int t = __shfl_up_sync(0xFFFFFFFFu, y, d);
            if (lane >= d) y += t;
        }
        warp_sums[lane] = y;
    }
    __syncthreads();

    int block_incl  = x + (wid > 0 ? warp_sums[wid - 1] : 0);
    int block_total = warp_sums[31];

    if (tid == 0) {
        if (bid == 0) {
            s_prefix = 0;
            atomicExch(&g_state[0], (2u << 28) | (unsigned)block_total);
        } else {
            atomicExch(&g_state[bid], (1u << 28) | (unsigned)block_total);
            int run = 0;
            int j = bid - 1;
            while (true) {
                unsigned st = atomicAdd(&g_state[j], 0u);
                unsigned f = st >> 28;
                if (f == 0) { __nanosleep(40); continue; }
                run += (int)(st & 0x0FFFFFFFu);
                if (f == 2u) break;
                j--;
            }
            s_prefix = run;
            atomicExch(&g_state[bid], (2u << 28) | (unsigned)(run + block_total));
        }
        if (bid == (int)gridDim.x - 1)
            g_off[N] = s_prefix + block_total;        // total padded edges
    }
    __syncthreads();

    int ex = s_prefix + block_incl - vp;              // exclusive prefix (16-aligned)
    if (i < N) { g_off[i] = ex; g_cur[i] = ex; }
}

// ---------- scatter: 4 independent atomics per thread ----------
__global__ void k_build(const int* __restrict__ row, const int* __restrict__ col, int E) {
    int t = blockIdx.x * blockDim.x + threadIdx.x;
    int stride = gridDim.x * blockDim.x;
    #pragma unroll
    for (int j = 0; j < 4; j++) {
        int e = t + j * stride;
        if (e < E) {
            int pos = atomicAdd(&g_cur[row[e]], 1);
            g_csr[pos] = col[e];
        }
    }
}

// ------------------- GEMM: hs = (in @ W) * dinv[row], fp16 out -------------------
#define GEMM_ROWS 64

__global__ __launch_bounds__(256)
void k_gemm(const float* __restrict__ in, const float* __restrict__ W,
            __half* __restrict__ out, int N)
{
    __shared__ float Wt[64][66];     // [c][k], padded: 8B aligned, conflict-free
    __shared__ float Xs[GEMM_ROWS][64];

    int tid = threadIdx.x;
    int row0 = blockIdx.x * GEMM_ROWS;

    #pragma unroll
    for (int i = tid; i < 64 * 64; i += 256) {
        int k = i >> 6, c = i & 63;
        Wt[c][k] = W[i];
    }

    #pragma unroll
    for (int i = tid; i < GEMM_ROWS * 16; i += 256) {
        int r = i >> 4, k4 = (i & 15);
        int gr = row0 + r;
        float4 v = (gr < N) ? reinterpret_cast<const float4*>(in)[(size_t)gr * 16 + k4]
                            : make_float4(0.f, 0.f, 0.f, 0.f);
        reinterpret_cast<float4*>(&Xs[r][0])[k4] = v;
    }
    __syncthreads();

    int cg = tid & 15;
    int rg = tid >> 4;
    int r0 = rg * 4;

    unsigned long long acc[4][4];
    #pragma unroll
    for (int a = 0; a < 4; a++)
        #pragma unroll
        for (int b = 0; b < 4; b++)
            acc[a][b] = 0ULL;

    #pragma unroll 8
    for (int kp = 0; kp < 32; kp++) {
        unsigned long long xv[4], wv[4];
        #pragma unroll
        for (int a = 0; a < 4; a++)
            xv[a] = *reinterpret_cast<const unsigned long long*>(&Xs[r0 + a][kp * 2]);
        #pragma unroll
        for (int b = 0; b < 4; b++)
            wv[b] = *reinterpret_cast<const unsigned long long*>(&Wt[cg + 16 * b][kp * 2]);
        #pragma unroll
        for (int a = 0; a < 4; a++)
            #pragma unroll
            for (int b = 0; b < 4; b++)
                asm("fma.rn.f32x2 %0, %1, %2, %0;"
                    : "+l"(acc[a][b]) : "l"(xv[a]), "l"(wv[b]));
    }

    #pragma unroll
    for (int a = 0; a < 4; a++) {
        int gr = row0 + r0 + a;
        if (gr < N) {
            float di = g_dinv[gr];
            #pragma unroll
            for (int b = 0; b < 4; b++) {
                float lo, hi;
                asm("mov.b64 {%0,%1}, %2;" : "=f"(lo), "=f"(hi) : "l"(acc[a][b]));
                out[(size_t)gr * 64 + cg + 16 * b] = __float2half_rn((lo + hi) * di);
            }
        }
    }
}

// ------------------- pull aggregation (fp16 gathers, fp32 accumulate) ----------
__global__ __launch_bounds__(256)
void k_pull(const __half* __restrict__ h, const float* __restrict__ bias,
            float* __restrict__ out, int N,
            const float* __restrict__ gam, const float* __restrict__ bet,
            const float* __restrict__ mu,  const float* __restrict__ var,
            int use_bn)
{
    int idx = blockIdx.x * blockDim.x + threadIdx.x;
    if (idx >= N * 16) return;
    int i = idx >> 4, k = idx & 15;

    const uint2* h2 = reinterpret_cast<const uint2*>(h);   // 16 uint2 per row

    float4 acc;
    {   // self term
        uint2 sv = __ldg(&h2[(size_t)i * 16 + k]);
        float2 f0 = __half22float2(*reinterpret_cast<__half2*>(&sv.x));
        float2 f1 = __half22float2(*reinterpret_cast<__half2*>(&sv.y));
        acc.x = f0.x; acc.y = f0.y; acc.z = f1.x; acc.w = f1.y;
    }

    int p   = g_off[i];
    int end = g_off[i + 1];

    for (; p < end; p += 16) {
        const int4* c4 = reinterpret_cast<const int4*>(&g_csr[p]);   // 16B aligned
        int4 a0 = __ldg(c4 + 0);
        int4 a1 = __ldg(c4 + 1);
        int4 a2 = __ldg(c4 + 2);
        int4 a3 = __ldg(c4 + 3);
        int cj[16] = { a0.x, a0.y, a0.z, a0.w,
                       a1.x, a1.y, a1.z, a1.w,
                       a2.x, a2.y, a2.z, a2.w,
                       a3.x, a3.y, a3.z, a3.w };

        #pragma unroll
        for (int jp = 0; jp < 8; jp++) {
            uint2 v0 = __ldg(&h2[(size_t)cj[2 * jp]     * 16 + k]);
            uint2 v1 = __ldg(&h2[(size_t)cj[2 * jp + 1] * 16 + k]);
            __half2 s0 = __hadd2(*reinterpret_cast<__half2*>(&v0.x),
                                 *reinterpret_cast<__half2*>(&v1.x));
            __half2 s1 = __hadd2(*reinterpret_cast<__half2*>(&v0.y),
                                 *reinterpret_cast<__half2*>(&v1.y));
            float2 f0 = __half22float2(s0);
            float2 f1 = __half22float2(s1);
            acc.x += f0.x; acc.y += f0.y; acc.z += f1.x; acc.w += f1.y;
        }
    }

    float di = g_dinv[i];
    float4 bv = reinterpret_cast<const float4*>(bias)[k];
    acc.x = fmaf(acc.x, di, bv.x);
    acc.y = fmaf(acc.y, di, bv.y);
    acc.z = fmaf(acc.z, di, bv.z);
    acc.w = fmaf(acc.w, di, bv.w);

    if (use_bn) {
        int k4 = k << 2;
        #pragma unroll
        for (int j = 0; j < 4; j++) {
            float a = gam[k4 + j] * rsqrtf(var[k4 + j] + EPS);
            float c = bet[k4 + j] - mu[k4 + j] * a;
            float* f = (&acc.x) + j;
            *f = fmaxf(fmaf(*f, a, c), 0.0f);
        }
    }

    reinterpret_cast<float4*>(out)[(size_t)i * 16 + k] = acc;
}

// ------------------- launch (forked-graph orchestration) -------------------
extern "C" void kernel_launch(void* const* d_in, const int* in_sizes, int n_in,
                              void* d_out, int out_size)
{
    const float* x   = (const float*)d_in[0];
    const int*   ei  = (const int*)  d_in[1];
    const float* W1  = (const float*)d_in[2];
    const float* b1  = (const float*)d_in[3];
    const float* g1  = (const float*)d_in[4];
    const float* be1 = (const float*)d_in[5];
    const float* m1  = (const float*)d_in[6];
    const float* v1  = (const float*)d_in[7];
    const float* W2  = (const float*)d_in[8];
    const float* b2  = (const float*)d_in[9];
    const float* g2  = (const float*)d_in[10];
    const float* be2 = (const float*)d_in[11];
    const float* m2  = (const float*)d_in[12];
    const float* v2  = (const float*)d_in[13];
    const float* W3  = (const float*)d_in[14];
    const float* b3  = (const float*)d_in[15];

    int N = in_sizes[0] / 64;
    int E = in_sizes[1] / 2;

    const int* row = ei;
    const int* col = ei + E;

    float* out  = (float*)d_out;
    float* emb  = out;                      // global_embeddings [N,64]
    float* pred = out + (size_t)N * 64;     // hc_predictions    [N,64]

    __half* p_h = nullptr;
    float*  p_agg = nullptr;
    cudaGetSymbolAddress((void**)&p_h,   g_h);
    cudaGetSymbolAddress((void**)&p_agg, g_agg);

    // lazily-created side streams/events (host objects, created outside capture
    // on the first (correctness) call; reused identically on every call)
    static cudaStream_t sA = nullptr, sB = nullptr;
    static cudaEvent_t evFork = nullptr, evScan = nullptr, evA = nullptr, evB = nullptr;
    if (sA == nullptr) {
        cudaStreamCreateWithFlags(&sA, cudaStreamNonBlocking);
        cudaStreamCreateWithFlags(&sB, cudaStreamNonBlocking);
        cudaEventCreateWithFlags(&evFork, cudaEventDisableTiming);
        cudaEventCreateWithFlags(&evScan, cudaEventDisableTiming);
        cudaEventCreateWithFlags(&evA,    cudaEventDisableTiming);
        cudaEventCreateWithFlags(&evB,    cudaEventDisableTiming);
    }

    const int T = 256;
    int gZ   = (N + T - 1) / T;
    int gC   = (CSRMAX / 4 + T - 1) / T;
    int gE4  = (E + 4 * T - 1) / (4 * T);
    int gN16 = (N * 16 + T - 1) / T;
    int gG   = (N + GEMM_ROWS - 1) / GEMM_ROWS;
    int nb   = (N + SCAN_BLK - 1) / SCAN_BLK;

    // fork point
    cudaEventRecord(evFork, 0);
    cudaStreamWaitEvent(sA, evFork, 0);

    // branch A (parallel with everything): CSR padding prefill
    k_zeroCSR<<<gC, T, 0, sA>>>();
    cudaEventRecord(evA, sA);

    // branch 0 (main): deg/state/dummy zero -> count -> scan(+dinv) -> build
    k_zeroA  <<<gZ,  T>>>(N);
    k_count  <<<gE4, T>>>(row, E);
    k_scan_lb<<<nb, SCAN_BLK>>>(N);
    cudaEventRecord(evScan, 0);
    k_build  <<<gE4, T>>>(row, col, E);

    // branch B: gemm1 needs only dinv (from scan) -> runs concurrently with build
    cudaStreamWaitEvent(sB, evScan, 0);
    k_gemm<<<gG, T, 0, sB>>>(x, W1, p_h, N);
    cudaEventRecord(evB, sB);

    // join: pull1 needs csr (build + prefill) and h (gemm1)
    cudaStreamWaitEvent(0, evA, 0);
    cudaStreamWaitEvent(0, evB, 0);

    // ---- layer 1 aggregation: h = relu(bn1(agg + b1)) ----
    k_pull<<<gN16, T>>>(p_h, b1, p_agg, N, g1, be1, m1, v1, 1);

    // ---- layer 2: emb = relu(bn2(conv(h, W2) + b2)) -> d_out[0:N*64] ----
    k_gemm<<<gG,   T>>>(p_agg, W2, p_h, N);
    k_pull<<<gN16, T>>>(p_h, b2, emb, N, g2, be2, m2, v2, 1);

    // ---- layer 3: pred = conv(emb, W3) + b3 -> d_out[N*64:] ----
    k_gemm<<<gG,   T>>>(emb, W3, p_h, N);
    k_pull<<<gN16, T>>>(p_h, b3, pred, N, nullptr, nullptr, nullptr, nullptr, 0);
}